// round 1
// baseline (speedup 1.0000x reference)
#include <cuda_runtime.h>

// UndistortLayer: B=16, C=3, H=W=512, fp32.
// Per output pixel (b,y,x):
//   xur = (x-dx)/W - 0.5 ; yur = (y-dy)/H - 0.5
//   inv = 1/(1 - k*(xur^2+yur^2))            [== rd/ru, no atan2/cos/sin needed]
//   xd = (xur*inv + 0.5)*W + dx ; yd = (yur*inv + 0.5)*H + dy
//   bilinear gather with clamped floor/ceil corners, shared across 3 channels.

#define UD_B 16
#define UD_C 3
#define UD_H 512
#define UD_W 512
#define UD_HW (UD_H * UD_W)          // 262144 = 2^18
#define UD_CHW (UD_C * UD_HW)
#define PIX_PER_THREAD 4

__global__ __launch_bounds__(256) void undistort_kernel(
    const float* __restrict__ im,   // [B, C, H, W]
    const float* __restrict__ kArr, // [B]
    const float* __restrict__ dxArr,// [B]
    const float* __restrict__ dyArr,// [B]
    float* __restrict__ out)        // [B, C, H, W]
{
    const int tid = blockIdx.x * blockDim.x + threadIdx.x;
    const int pix0 = tid * PIX_PER_THREAD;          // first pixel of this thread
    // pix0 layout: b * HW + y * W + x, with x a multiple of 4.
    const int b   = pix0 >> 18;                     // / HW
    const int rem = pix0 & (UD_HW - 1);
    const int y   = rem >> 9;                       // / W
    const int x0  = rem & (UD_W - 1);

    const float k  = __ldg(&kArr[b]);
    const float dx = __ldg(&dxArr[b]);
    const float dy = __ldg(&dyArr[b]);

    const float invW = 1.0f / (float)UD_W;
    const float invH = 1.0f / (float)UD_H;

    const float yur = ((float)y - dy) * invH - 0.5f;
    const float yur2 = yur * yur;

    const float* imb = im + (size_t)b * UD_CHW;

    float acc[UD_C][PIX_PER_THREAD];

    #pragma unroll
    for (int p = 0; p < PIX_PER_THREAD; ++p) {
        const float xf32 = (float)(x0 + p);
        const float xur = (xf32 - dx) * invW - 0.5f;
        const float ru2 = xur * xur + yur2;
        const float inv = 1.0f / (1.0f - k * ru2);

        const float xd = (xur * inv + 0.5f) * (float)UD_W + dx;
        const float yd = (yur * inv + 0.5f) * (float)UD_H + dy;

        const float fx = floorf(xd);
        const float fy = floorf(yd);
        const float ox = xd - fx;
        const float oy = yd - fy;

        int xfi = (int)fx;
        int xci = (int)ceilf(xd);
        int yfi = (int)fy;
        int yci = (int)ceilf(yd);
        xfi = min(max(xfi, 0), UD_W - 1);
        xci = min(max(xci, 0), UD_W - 1);
        yfi = min(max(yfi, 0), UD_H - 1);
        yci = min(max(yci, 0), UD_H - 1);

        const int i00 = yfi * UD_W + xfi;
        const int i01 = yfi * UD_W + xci;
        const int i10 = yci * UD_W + xfi;
        const int i11 = yci * UD_W + xci;

        const float w00 = (1.0f - ox) * (1.0f - oy);
        const float w01 = ox * (1.0f - oy);
        const float w10 = (1.0f - ox) * oy;
        const float w11 = ox * oy;

        #pragma unroll
        for (int c = 0; c < UD_C; ++c) {
            const float* plane = imb + c * UD_HW;
            const float v00 = __ldg(plane + i00);
            const float v01 = __ldg(plane + i01);
            const float v10 = __ldg(plane + i10);
            const float v11 = __ldg(plane + i11);
            acc[c][p] = w00 * v00 + w01 * v01 + w10 * v10 + w11 * v11;
        }
    }

    // Coalesced float4 stores, one per channel.
    const size_t obase = (size_t)b * UD_CHW + (size_t)y * UD_W + x0;
    #pragma unroll
    for (int c = 0; c < UD_C; ++c) {
        float4 v = make_float4(acc[c][0], acc[c][1], acc[c][2], acc[c][3]);
        *reinterpret_cast<float4*>(out + obase + (size_t)c * UD_HW) = v;
    }
}

extern "C" void kernel_launch(void* const* d_in, const int* in_sizes, int n_in,
                              void* d_out, int out_size) {
    const float* im = (const float*)d_in[0];
    const float* k  = (const float*)d_in[1];
    const float* dx = (const float*)d_in[2];
    const float* dy = (const float*)d_in[3];
    float* out = (float*)d_out;

    const int total_pix = UD_B * UD_HW;                 // 4,194,304
    const int threads = total_pix / PIX_PER_THREAD;     // 1,048,576
    const int block = 256;
    const int grid = threads / block;                   // 4096
    undistort_kernel<<<grid, block>>>(im, k, dx, dy, out);
}